// round 1
// baseline (speedup 1.0000x reference)
#include <cuda_runtime.h>
#include <cuda_bf16.h>
#include <math.h>

// Problem constants (fixed by reference setup_inputs)
#define NB   16
#define CH   64
#define HH   128
#define WW   128
#define PLANE (HH*WW)          // 16384
#define GK2  72                // GROUP*KSIZE*KSIZE
#define BN_EPS 1e-5f

// Scratch (allocation-free rule: __device__ globals)
__device__ float g_pooled[NB * CH];    // (n, c) means
__device__ float g_f[NB * GK2];        // (n, 72) softmaxed weights

// ---------------------------------------------------------------------------
// Kernel 1: adaptive avg pool -> pooled[n*64+c]
// One CTA per (n,c) plane; float4 loads, warp + smem reduce.
// ---------------------------------------------------------------------------
__global__ void __launch_bounds__(256) pool_kernel(const float* __restrict__ x) {
    const int p = blockIdx.x;                     // n*CH + c
    const float4* xp = (const float4*)(x + (size_t)p * PLANE);
    float s = 0.f;
    #pragma unroll 4
    for (int i = threadIdx.x; i < PLANE / 4; i += 256) {
        float4 v = xp[i];
        s += (v.x + v.y) + (v.z + v.w);
    }
    #pragma unroll
    for (int o = 16; o > 0; o >>= 1) s += __shfl_xor_sync(0xffffffffu, s, o);
    __shared__ float ws[8];
    if ((threadIdx.x & 31) == 0) ws[threadIdx.x >> 5] = s;
    __syncthreads();
    if (threadIdx.x < 8) {
        s = ws[threadIdx.x];
        #pragma unroll
        for (int o = 4; o > 0; o >>= 1) s += __shfl_xor_sync(0x000000ffu, s, o);
        if (threadIdx.x == 0) g_pooled[p] = s * (1.f / (float)PLANE);
    }
}

// ---------------------------------------------------------------------------
// Kernel 2: f = softmax_over_9( BN( pooled @ conv_w^T ) )
// 16 blocks (one per n), 72 threads (one per output feature).
// ---------------------------------------------------------------------------
__global__ void weights_kernel(const float* __restrict__ conv_w,
                               const float* __restrict__ gamma,
                               const float* __restrict__ beta,
                               const float* __restrict__ mean,
                               const float* __restrict__ var) {
    const int n = blockIdx.x;
    const int j = threadIdx.x;                    // 0..71
    const float* pn = g_pooled + n * CH;
    const float* wj = conv_w + j * CH;
    float acc = 0.f;
    #pragma unroll
    for (int c = 0; c < CH; c++) acc = fmaf(pn[c], wj[c], acc);
    acc = gamma[j] * (acc - mean[j]) * rsqrtf(var[j] + BN_EPS) + beta[j];

    __shared__ float s[GK2];
    s[j] = acc;
    __syncthreads();

    const int g = j / 9;
    const float* sg = s + g * 9;
    float m = sg[0];
    #pragma unroll
    for (int i = 1; i < 9; i++) m = fmaxf(m, sg[i]);
    float sum = 0.f;
    #pragma unroll
    for (int i = 0; i < 9; i++) sum += __expf(sg[i] - m);
    g_f[n * GK2 + j] = __expf(acc - m) / sum;
}

// ---------------------------------------------------------------------------
// Kernel 3: low = 3x3 reflect-pad weighted sum; out = [low ; x - low]
// One CTA per (n,c) plane; whole plane staged in 64 KB dynamic smem.
// Streaming (__stcs) float4 stores to avoid evicting x from L2.
// ---------------------------------------------------------------------------
__global__ void __launch_bounds__(512) decouple_kernel(const float* __restrict__ x,
                                                       float* __restrict__ out) {
    extern __shared__ float tile[];               // PLANE floats = 64 KB
    const int p = blockIdx.x;                     // n*CH + c
    const int n = p >> 6;
    const int c = p & 63;
    const int g = c >> 3;                         // group = c / (CH/GROUP)

    // load the 9 weights for this plane
    const float* fw = g_f + n * GK2 + g * 9;
    float w[9];
    #pragma unroll
    for (int k = 0; k < 9; k++) w[k] = fw[k];

    const size_t base = (size_t)p * PLANE;
    const float4* xin = (const float4*)(x + base);
    float4* t4 = (float4*)tile;
    #pragma unroll 2
    for (int i = threadIdx.x; i < PLANE / 4; i += 512) t4[i] = xin[i];
    __syncthreads();

    float4* olow = (float4*)(out + base);
    float4* ores = (float4*)(out + (size_t)NB * CH * PLANE + base);

    #pragma unroll 2
    for (int i = threadIdx.x; i < PLANE / 4; i += 512) {
        const int y  = i >> 5;                    // row (128 cols / 4 = 32 chunks)
        const int x0 = (i & 31) * 4;              // first col of float4 chunk
        const int ym = (y == 0)      ? 1       : y - 1;
        const int yp = (y == HH - 1) ? HH - 2  : y + 1;
        const float* r0 = tile + ym * WW;
        const float* r1 = tile + y  * WW;
        const float* r2 = tile + yp * WW;

        float lo[4], rs[4];
        #pragma unroll
        for (int k = 0; k < 4; k++) {
            const int xx = x0 + k;
            const int xm = (xx == 0)      ? 1      : xx - 1;
            const int xp = (xx == WW - 1) ? WW - 2 : xx + 1;
            const float v = r1[xx];
            float acc;
            acc = r0[xm] * w[0];
            acc = fmaf(r0[xx], w[1], acc);
            acc = fmaf(r0[xp], w[2], acc);
            acc = fmaf(r1[xm], w[3], acc);
            acc = fmaf(v,      w[4], acc);
            acc = fmaf(r1[xp], w[5], acc);
            acc = fmaf(r2[xm], w[6], acc);
            acc = fmaf(r2[xx], w[7], acc);
            acc = fmaf(r2[xp], w[8], acc);
            lo[k] = acc;
            rs[k] = v - acc;
        }
        float4 L = make_float4(lo[0], lo[1], lo[2], lo[3]);
        float4 R = make_float4(rs[0], rs[1], rs[2], rs[3]);
        __stcs(olow + i, L);
        __stcs(ores + i, R);
    }
}

// ---------------------------------------------------------------------------
extern "C" void kernel_launch(void* const* d_in, const int* in_sizes, int n_in,
                              void* d_out, int out_size) {
    const float* x      = (const float*)d_in[0];
    const float* conv_w = (const float*)d_in[1];
    const float* gamma  = (const float*)d_in[2];
    const float* beta   = (const float*)d_in[3];
    const float* mean   = (const float*)d_in[4];
    const float* var    = (const float*)d_in[5];
    float* out = (float*)d_out;

    const int smem = PLANE * sizeof(float);       // 65536 bytes
    cudaFuncSetAttribute(decouple_kernel,
                         cudaFuncAttributeMaxDynamicSharedMemorySize, smem);

    pool_kernel<<<NB * CH, 256>>>(x);
    weights_kernel<<<NB, GK2>>>(conv_w, gamma, beta, mean, var);
    decouple_kernel<<<NB * CH, 512, smem>>>(x, out);
}

// round 2
// speedup vs baseline: 1.1613x; 1.1613x over previous
#include <cuda_runtime.h>
#include <cuda_bf16.h>
#include <math.h>

#define NB   16
#define CH   64
#define HH   128
#define WW   128
#define PLANE (HH*WW)          // 16384
#define GK2  72
#define BN_EPS 1e-5f

__device__ float g_pooled[NB * CH];
__device__ float g_f[NB * GK2];

// ---------------------------------------------------------------------------
// Kernel 1: adaptive avg pool. One CTA per plane, 256 thr, 16 fully-unrolled
// independent float4 loads per thread (MLP ~16).
// ---------------------------------------------------------------------------
__global__ void __launch_bounds__(256) pool_kernel(const float* __restrict__ x) {
    const int p = blockIdx.x;
    const float4* xp = (const float4*)(x + (size_t)p * PLANE);
    float s = 0.f;
    #pragma unroll
    for (int j = 0; j < 16; j++) {
        float4 v = xp[threadIdx.x + j * 256];
        s += (v.x + v.y) + (v.z + v.w);
    }
    #pragma unroll
    for (int o = 16; o > 0; o >>= 1) s += __shfl_xor_sync(0xffffffffu, s, o);
    __shared__ float ws[8];
    if ((threadIdx.x & 31) == 0) ws[threadIdx.x >> 5] = s;
    __syncthreads();
    if (threadIdx.x < 8) {
        s = ws[threadIdx.x];
        #pragma unroll
        for (int o = 4; o > 0; o >>= 1) s += __shfl_xor_sync(0x000000ffu, s, o);
        if (threadIdx.x == 0) g_pooled[p] = s * (1.f / (float)PLANE);
    }
}

// ---------------------------------------------------------------------------
// Kernel 2: f = softmax_9( BN( pooled @ conv_w^T ) ).  16 x 72 threads.
// ---------------------------------------------------------------------------
__global__ void weights_kernel(const float* __restrict__ conv_w,
                               const float* __restrict__ gamma,
                               const float* __restrict__ beta,
                               const float* __restrict__ mean,
                               const float* __restrict__ var) {
    const int n = blockIdx.x;
    const int j = threadIdx.x;                    // 0..71
    const float* pn = g_pooled + n * CH;
    const float* wj = conv_w + j * CH;
    float acc = 0.f;
    #pragma unroll
    for (int c = 0; c < CH; c++) acc = fmaf(pn[c], wj[c], acc);
    acc = gamma[j] * (acc - mean[j]) * rsqrtf(var[j] + BN_EPS) + beta[j];

    __shared__ float s[GK2];
    s[j] = acc;
    __syncthreads();

    const int g = j / 9;
    const float* sg = s + g * 9;
    float m = sg[0];
    #pragma unroll
    for (int i = 1; i < 9; i++) m = fmaxf(m, sg[i]);
    float sum = 0.f;
    #pragma unroll
    for (int i = 0; i < 9; i++) sum += __expf(sg[i] - m);
    g_f[n * GK2 + j] = __expf(acc - m) / sum;
}

// ---------------------------------------------------------------------------
// Kernel 3: warp-per-row 3x3 weighted sum, conflict-free LDS.128 + shuffles.
// ---------------------------------------------------------------------------
__device__ __forceinline__ void row_taps(float4 v, int lane, float wl, float wc, float wr,
                                         float acc[4]) {
    float left  = __shfl_up_sync(0xffffffffu, v.w, 1);
    float right = __shfl_down_sync(0xffffffffu, v.x, 1);
    if (lane == 0)  left  = v.y;   // reflect x[-1] -> x[1]
    if (lane == 31) right = v.z;   // reflect x[128] -> x[126]
    acc[0] = fmaf(left, wl, fmaf(v.x, wc, fmaf(v.y, wr, acc[0])));
    acc[1] = fmaf(v.x,  wl, fmaf(v.y, wc, fmaf(v.z, wr, acc[1])));
    acc[2] = fmaf(v.y,  wl, fmaf(v.z, wc, fmaf(v.w, wr, acc[2])));
    acc[3] = fmaf(v.z,  wl, fmaf(v.w, wc, fmaf(right, wr, acc[3])));
}

__global__ void __launch_bounds__(512) decouple_kernel(const float* __restrict__ x,
                                                       float* __restrict__ out) {
    extern __shared__ float tile[];               // 64 KB plane
    const int p = blockIdx.x;
    const int n = p >> 6;
    const int c = p & 63;
    const int g = c >> 3;

    const float* fw = g_f + n * GK2 + g * 9;
    float w[9];
    #pragma unroll
    for (int k = 0; k < 9; k++) w[k] = fw[k];

    const size_t base = (size_t)p * PLANE;
    const float4* xin = (const float4*)(x + base);
    float4* t4 = (float4*)tile;
    #pragma unroll
    for (int j = 0; j < 8; j++) t4[threadIdx.x + j * 512] = xin[threadIdx.x + j * 512];
    __syncthreads();

    float4* olow = (float4*)(out + base);
    float4* ores = (float4*)(out + (size_t)NB * CH * PLANE + base);

    const int lane = threadIdx.x & 31;
    const int warp = threadIdx.x >> 5;            // 0..15

    #pragma unroll
    for (int iter = 0; iter < 8; iter++) {
        const int y  = iter * 16 + warp;
        const int ym = (y == 0)      ? 1        : y - 1;
        const int yp = (y == HH - 1) ? HH - 2   : y + 1;

        float4 va = t4[ym * (WW / 4) + lane];
        float4 vb = t4[y  * (WW / 4) + lane];
        float4 vc = t4[yp * (WW / 4) + lane];

        float acc[4] = {0.f, 0.f, 0.f, 0.f};
        row_taps(va, lane, w[0], w[1], w[2], acc);
        row_taps(vb, lane, w[3], w[4], w[5], acc);
        row_taps(vc, lane, w[6], w[7], w[8], acc);

        float4 L = make_float4(acc[0], acc[1], acc[2], acc[3]);
        float4 R = make_float4(vb.x - acc[0], vb.y - acc[1],
                               vb.z - acc[2], vb.w - acc[3]);
        const int oi = y * (WW / 4) + lane;
        __stcs(olow + oi, L);
        __stcs(ores + oi, R);
    }
}

// ---------------------------------------------------------------------------
extern "C" void kernel_launch(void* const* d_in, const int* in_sizes, int n_in,
                              void* d_out, int out_size) {
    const float* x      = (const float*)d_in[0];
    const float* conv_w = (const float*)d_in[1];
    const float* gamma  = (const float*)d_in[2];
    const float* beta   = (const float*)d_in[3];
    const float* mean   = (const float*)d_in[4];
    const float* var    = (const float*)d_in[5];
    float* out = (float*)d_out;

    const int smem = PLANE * sizeof(float);
    cudaFuncSetAttribute(decouple_kernel,
                         cudaFuncAttributeMaxDynamicSharedMemorySize, smem);

    pool_kernel<<<NB * CH, 256>>>(x);
    weights_kernel<<<NB, GK2>>>(conv_w, gamma, beta, mean, var);
    decouple_kernel<<<NB * CH, 512, smem>>>(x, out);
}